// round 6
// baseline (speedup 1.0000x reference)
#include <cuda_runtime.h>
#include <cuda_fp16.h>

#define NN 50000
#define EE 800000
#define GG 128
#define FIN 16
#define HH 64
#define LL 63
#define GRID_GC ((NN + 63) / 64)
#define TILE 1024
#define NT ((NN + TILE - 1) / TILE)   // 49
#define E4 (EE / 4)                   // 200000
#define GRID_E4 ((E4 + 255) / 256)    // 782
#define ZB ((NN + 255) / 256)         // 196

// ---------------- scratch (device globals; no allocations) ----------------
__device__ int g_hist[NN];
__device__ int g_off[NN + 1];
__device__ int g_cursor[NN];
__device__ int g_srt[EE];
__device__ __align__(16) __half g_h1[NN * HH];
__device__ float g_s[NN];
__device__ float g_poolS[GG], g_poolT[GG];
__device__ float g_urel[HH], g_uroot[HH];
__device__ float g_e;

// ---------------- zero + conv1d/GC3 fold (extra block) ----------------
__global__ void k_zero(const float* __restrict__ w, const float* __restrict__ b,
                       const float* __restrict__ Wrel3, const float* __restrict__ brel3,
                       const float* __restrict__ Wroot3) {
    int t = threadIdx.x;
    if (blockIdx.x < ZB) {
        int i = blockIdx.x * 256 + t;
        if (i < NN) g_hist[i] = 0;
        if (i < GG) { g_poolS[i] = 0.f; g_poolT[i] = 0.f; }
        if (i == 0) g_off[NN] = EE;
        return;
    }
    // fold block: 63 Conv1d layers + GraphConv3 -> (u_rel, u_root, e)
    __shared__ float swb[3 * LL];   // w[126], b[63]
    __shared__ float sc[HH];
    if (t < 2 * LL) swb[t] = w[t];
    else if (t < 3 * LL) swb[t] = b[t - 2 * LL];
    __syncthreads();
    float dacc = 0.f;
    if (t < 32) {
        float clo = (t == 0) ? 1.f : 0.f, chi = 0.f;
        float Ssum = 1.f;
        #pragma unroll 1
        for (int i = LL - 1; i >= 0; --i) {
            float w0 = swb[2 * i], w1 = swb[2 * i + 1];
            dacc = fmaf(swb[2 * LL + i], Ssum, dacc);
            Ssum *= (w0 + w1);
            float ph = __shfl_up_sync(0xffffffffu, chi, 1);
            if (t == 0) ph = 0.f;
            float nlo = fmaf(w0, clo, w1 * ph);
            float nhi = fmaf(w0, chi, w1 * clo);
            clo = nlo; chi = nhi;
        }
        sc[2 * t] = clo;
        sc[2 * t + 1] = chi;
    }
    __syncthreads();
    if (t < HH) {
        float ur = 0.f, uo = 0.f;
        #pragma unroll 8
        for (int k = 0; k < HH; k++) {
            ur = fmaf(Wrel3[t * HH + k], sc[k], ur);
            uo = fmaf(Wroot3[t * HH + k], sc[k], uo);
        }
        g_urel[t] = ur;
        g_uroot[t] = uo;
    }
    if (t == 0) {
        float e = dacc;
        #pragma unroll 8
        for (int k = 0; k < HH; k++) e = fmaf(brel3[k], sc[k], e);
        g_e = e;
    }
}

// ---------------- histogram of dst (4 edges / thread) ----------------
__global__ void __launch_bounds__(256) k_hist(const int* __restrict__ ei) {
    int tid = blockIdx.x * 256 + threadIdx.x;
    if (tid < E4) {
        int4 d = ((const int4*)(ei + EE))[tid];
        atomicAdd(&g_hist[d.x], 1);
        atomicAdd(&g_hist[d.y], 1);
        atomicAdd(&g_hist[d.z], 1);
        atomicAdd(&g_hist[d.w], 1);
    }
}

// ---------------- tile scan with self-computed tile offset ----------------
__global__ void __launch_bounds__(1024) k_scan() {
    __shared__ int ws[32];
    __shared__ int ws2[32];
    __shared__ int stoff;
    int t = threadIdx.x;
    int lane = t & 31, wid = t >> 5;
    int base = blockIdx.x * TILE;
    int i = base + t;
    int v = (i < NN) ? g_hist[i] : 0;
    int inc = v;
    #pragma unroll
    for (int d = 1; d < 32; d <<= 1) {
        int n = __shfl_up_sync(0xffffffffu, inc, d);
        if (lane >= d) inc += n;
    }
    if (lane == 31) ws[wid] = inc;
    // tile offset: block-reduce hist[0 .. base)
    int loc = 0;
    for (int j = t; j < base; j += 1024) loc += g_hist[j];
    #pragma unroll
    for (int d = 16; d > 0; d >>= 1) loc += __shfl_down_sync(0xffffffffu, loc, d);
    if (lane == 0) ws2[wid] = loc;
    __syncthreads();
    if (wid == 0) {
        int s = ws[lane];
        int si = s;
        #pragma unroll
        for (int d = 1; d < 32; d <<= 1) {
            int n = __shfl_up_sync(0xffffffffu, si, d);
            if (lane >= d) si += n;
        }
        ws[lane] = si - s;
        int r = ws2[lane];
        #pragma unroll
        for (int d = 16; d > 0; d >>= 1) r += __shfl_down_sync(0xffffffffu, r, d);
        if (lane == 0) stoff = r;
    }
    __syncthreads();
    if (i < NN) {
        int excl = inc - v + ws[wid] + stoff;
        g_off[i] = excl;
        g_cursor[i] = excl;
    }
}

// ---------------- build sorted src list (4 edges / thread) ----------------
__global__ void __launch_bounds__(256) k_build(const int* __restrict__ ei) {
    int tid = blockIdx.x * 256 + threadIdx.x;
    if (tid < E4) {
        int4 s4 = ((const int4*)ei)[tid];
        int4 d4 = ((const int4*)(ei + EE))[tid];
        int p0 = atomicAdd(&g_cursor[d4.x], 1);
        int p1 = atomicAdd(&g_cursor[d4.y], 1);
        int p2 = atomicAdd(&g_cursor[d4.z], 1);
        int p3 = atomicAdd(&g_cursor[d4.w], 1);
        g_srt[p0] = s4.x;
        g_srt[p1] = s4.y;
        g_srt[p2] = s4.z;
        g_srt[p3] = s4.w;
    }
}

// ---------------- GC1 fused: agg = CSR-gather(x); h1 = relu(...) -> fp16 ----------
__global__ void __launch_bounds__(256) k_gc1(const float* __restrict__ x,
                                             const float* __restrict__ Wrel,
                                             const float* __restrict__ brel,
                                             const float* __restrict__ Wroot) {
    __shared__ float swr[FIN * HH];
    __shared__ float swo[FIN * HH];
    __shared__ float sb[HH];
    __shared__ float sa[64 * 17];
    __shared__ float sx[64 * 20];
    __shared__ int sidx[8][32];
    int t = threadIdx.x;
    int node0 = blockIdx.x * 64;
    {
        const float4* wr4 = (const float4*)Wrel;
        const float4* wo4 = (const float4*)Wroot;
        float4* swr4 = (float4*)swr;
        float4* swo4 = (float4*)swo;
        if (t < FIN * HH / 4) { swr4[t] = wr4[t]; swo4[t] = wo4[t]; }
        if (t < HH) sb[t] = brel[t];
    }
    // stage root rows
    {
        float4 z = make_float4(0.f, 0.f, 0.f, 0.f);
        int r = t >> 2, q = t & 3;
        float4 v = (node0 + r < NN) ? ((const float4*)(x + (size_t)(node0 + r) * FIN))[q] : z;
        *(float4*)&sx[r * 20 + q * 4] = v;
    }
    // gather: warp per 8 nodes; staged indices + unrolled independent loads
    {
        int w = t >> 5, lane = t & 31;
        int col = lane & 15, half = lane >> 4;
        #pragma unroll
        for (int k = 0; k < 8; k++) {
            int ln = w * 8 + k;
            int node = node0 + ln;
            float acc = 0.f;
            if (node < NN) {
                int beg = g_off[node], end = g_off[node + 1];
                for (int base = beg; base < end; base += 32) {
                    int c = end - base; if (c > 32) c = 32;
                    if (lane < c) sidx[w][lane] = g_srt[base + lane];
                    __syncwarp();
                    int m = 0;
                    for (; m + 8 <= c; m += 8) {
                        int sA = sidx[w][m + half];
                        int sB = sidx[w][m + 2 + half];
                        int sC = sidx[w][m + 4 + half];
                        int sD = sidx[w][m + 6 + half];
                        float vA = __ldg(&x[(size_t)sA * FIN + col]);
                        float vB = __ldg(&x[(size_t)sB * FIN + col]);
                        float vC = __ldg(&x[(size_t)sC * FIN + col]);
                        float vD = __ldg(&x[(size_t)sD * FIN + col]);
                        acc += vA + vB + vC + vD;
                    }
                    for (; m + 2 <= c; m += 2)
                        acc += __ldg(&x[(size_t)sidx[w][m + half] * FIN + col]);
                    if (m < c && half == 0)
                        acc += __ldg(&x[(size_t)sidx[w][m] * FIN + col]);
                    __syncwarp();
                }
            }
            acc += __shfl_down_sync(0xffffffffu, acc, 16);
            if (lane < 16) sa[ln * 17 + col] = acc;
        }
    }
    __syncthreads();
    int kg = t & 15, ng = t >> 4;
    int k0 = kg * 4, n0 = ng * 4;
    float acc[4][4];
    #pragma unroll
    for (int i = 0; i < 4; i++) {
        acc[i][0] = sb[k0]; acc[i][1] = sb[k0 + 1]; acc[i][2] = sb[k0 + 2]; acc[i][3] = sb[k0 + 3];
    }
    #pragma unroll
    for (int j = 0; j < FIN; j++) {
        float4 wr = *(const float4*)&swr[j * HH + k0];
        float4 wo = *(const float4*)&swo[j * HH + k0];
        #pragma unroll
        for (int i = 0; i < 4; i++) {
            float av = sa[(n0 + i) * 17 + j];
            float xv = sx[(n0 + i) * 20 + j];
            acc[i][0] = fmaf(av, wr.x, fmaf(xv, wo.x, acc[i][0]));
            acc[i][1] = fmaf(av, wr.y, fmaf(xv, wo.y, acc[i][1]));
            acc[i][2] = fmaf(av, wr.z, fmaf(xv, wo.z, acc[i][2]));
            acc[i][3] = fmaf(av, wr.w, fmaf(xv, wo.w, acc[i][3]));
        }
    }
    #pragma unroll
    for (int i = 0; i < 4; i++) {
        int node = node0 + n0 + i;
        if (node < NN) {
            __half2 ha = __floats2half2_rn(fmaxf(acc[i][0], 0.f), fmaxf(acc[i][1], 0.f));
            __half2 hb = __floats2half2_rn(fmaxf(acc[i][2], 0.f), fmaxf(acc[i][3], 0.f));
            __half2* p = (__half2*)&g_h1[(size_t)node * HH + k0];
            p[0] = ha;
            p[1] = hb;
        }
    }
}

// ---------------- GC2 fused (two-pass shared buffer) + folded layer 3 -------------
__global__ void __launch_bounds__(256) k_gc2(const int* __restrict__ batch,
                                             const float* __restrict__ Wrel,
                                             const float* __restrict__ brel,
                                             const float* __restrict__ Wroot) {
    __shared__ float sw[HH * HH];
    __shared__ float st[64 * 68];
    __shared__ float sb[HH], su[HH], sv[HH];
    __shared__ float binsT[GG];
    __shared__ int sidx[8][32];
    int t = threadIdx.x;
    int node0 = blockIdx.x * 64;
    const __half2* h2p = (const __half2*)g_h1;   // HH/2 = 32 half2 per row
    {
        const float4* w4 = (const float4*)Wrel;
        float4* s4 = (float4*)sw;
        #pragma unroll
        for (int i = t; i < HH * HH / 4; i += 256) s4[i] = w4[i];
        if (t < HH) { sb[t] = brel[t]; su[t] = g_urel[t]; sv[t] = g_uroot[t]; }
        if (t < GG) binsT[t] = 0.f;
    }
    // gather agg2 rows: warp per 8 nodes; fp16 rows, fp32 accumulate
    {
        int w = t >> 5, lane = t & 31;
        #pragma unroll
        for (int k = 0; k < 8; k++) {
            int ln = w * 8 + k;
            int node = node0 + ln;
            float ax = 0.f, ay = 0.f;
            if (node < NN) {
                int beg = g_off[node], end = g_off[node + 1];
                for (int base = beg; base < end; base += 32) {
                    int c = end - base; if (c > 32) c = 32;
                    if (lane < c) sidx[w][lane] = g_srt[base + lane];
                    __syncwarp();
                    int m = 0;
                    for (; m + 4 <= c; m += 4) {
                        int s0 = sidx[w][m], s1 = sidx[w][m + 1];
                        int s2 = sidx[w][m + 2], s3 = sidx[w][m + 3];
                        float2 v0 = __half22float2(__ldg(&h2p[(size_t)s0 * 32 + lane]));
                        float2 v1 = __half22float2(__ldg(&h2p[(size_t)s1 * 32 + lane]));
                        float2 v2 = __half22float2(__ldg(&h2p[(size_t)s2 * 32 + lane]));
                        float2 v3 = __half22float2(__ldg(&h2p[(size_t)s3 * 32 + lane]));
                        ax += v0.x + v1.x + v2.x + v3.x;
                        ay += v0.y + v1.y + v2.y + v3.y;
                    }
                    for (; m < c; m++) {
                        float2 v0 = __half22float2(__ldg(&h2p[(size_t)sidx[w][m] * 32 + lane]));
                        ax += v0.x; ay += v0.y;
                    }
                    __syncwarp();
                }
            }
            *(float2*)&st[ln * 68 + lane * 2] = make_float2(ax, ay);
        }
    }
    __syncthreads();
    int kg = t & 15, ng = t >> 4;
    int k0 = kg * 4, n0 = ng * 4;
    float acc[4][4];
    #pragma unroll
    for (int i = 0; i < 4; i++) {
        acc[i][0] = sb[k0]; acc[i][1] = sb[k0 + 1]; acc[i][2] = sb[k0 + 2]; acc[i][3] = sb[k0 + 3];
    }
    // pass 1: rel GEMM on gathered agg
    #pragma unroll 4
    for (int j = 0; j < HH; j++) {
        float4 wr = *(const float4*)&sw[j * HH + k0];
        #pragma unroll
        for (int i = 0; i < 4; i++) {
            float av = st[(n0 + i) * 68 + j];
            acc[i][0] = fmaf(av, wr.x, acc[i][0]);
            acc[i][1] = fmaf(av, wr.y, acc[i][1]);
            acc[i][2] = fmaf(av, wr.z, acc[i][2]);
            acc[i][3] = fmaf(av, wr.w, acc[i][3]);
        }
    }
    __syncthreads();
    // restage: Wroot into sw, h1 rows into st
    {
        const float4* w4 = (const float4*)Wroot;
        float4* s4 = (float4*)sw;
        #pragma unroll
        for (int i = t; i < HH * HH / 4; i += 256) s4[i] = w4[i];
        #pragma unroll
        for (int idx = t; idx < 64 * 32; idx += 256) {
            int r = idx >> 5, p = idx & 31;
            float2 f = (node0 + r < NN)
                ? __half22float2(h2p[(size_t)(node0 + r) * 32 + p])
                : make_float2(0.f, 0.f);
            st[r * 68 + 2 * p] = f.x;
            st[r * 68 + 2 * p + 1] = f.y;
        }
    }
    __syncthreads();
    // pass 2: root GEMM
    #pragma unroll 4
    for (int j = 0; j < HH; j++) {
        float4 wo = *(const float4*)&sw[j * HH + k0];
        #pragma unroll
        for (int i = 0; i < 4; i++) {
            float hv = st[(n0 + i) * 68 + j];
            acc[i][0] = fmaf(hv, wo.x, acc[i][0]);
            acc[i][1] = fmaf(hv, wo.y, acc[i][1]);
            acc[i][2] = fmaf(hv, wo.z, acc[i][2]);
            acc[i][3] = fmaf(hv, wo.w, acc[i][3]);
        }
    }
    // epilogue: relu, fold into per-node scalars, pool T
    float u0 = su[k0], u1 = su[k0 + 1], u2 = su[k0 + 2], u3 = su[k0 + 3];
    float v0 = sv[k0], v1 = sv[k0 + 1], v2 = sv[k0 + 2], v3 = sv[k0 + 3];
    #pragma unroll
    for (int i = 0; i < 4; i++) {
        float h0 = fmaxf(acc[i][0], 0.f);
        float h1 = fmaxf(acc[i][1], 0.f);
        float h2 = fmaxf(acc[i][2], 0.f);
        float h3 = fmaxf(acc[i][3], 0.f);
        float sp = h0 * u0 + h1 * u1 + h2 * u2 + h3 * u3;
        float tp = h0 * v0 + h1 * v1 + h2 * v2 + h3 * v3;
        #pragma unroll
        for (int off = 8; off > 0; off >>= 1) {
            sp += __shfl_down_sync(0xffffffffu, sp, off, 16);
            tp += __shfl_down_sync(0xffffffffu, tp, off, 16);
        }
        if (kg == 0) {
            int node = node0 + n0 + i;
            if (node < NN) {
                g_s[node] = sp;
                atomicAdd(&binsT[batch[node]], tp);
            }
        }
    }
    __syncthreads();
    if (t < GG && binsT[t] != 0.f) atomicAdd(&g_poolT[t], binsT[t]);
}

// ---------------- scalar edge scatter into per-graph pool (4 edges / thread) ------
__global__ void __launch_bounds__(256) k_scatter3(const int* __restrict__ ei,
                                                  const int* __restrict__ batch) {
    __shared__ float bins[GG];
    int t = threadIdx.x;
    if (t < GG) bins[t] = 0.f;
    __syncthreads();
    int tid = blockIdx.x * 256 + t;
    if (tid < E4) {
        int4 s4 = ((const int4*)ei)[tid];
        int4 d4 = ((const int4*)(ei + EE))[tid];
        float v0 = g_s[s4.x], v1 = g_s[s4.y], v2 = g_s[s4.z], v3 = g_s[s4.w];
        int b0 = batch[d4.x], b1 = batch[d4.y], b2 = batch[d4.z], b3 = batch[d4.w];
        atomicAdd(&bins[b0], v0);
        atomicAdd(&bins[b1], v1);
        atomicAdd(&bins[b2], v2);
        atomicAdd(&bins[b3], v3);
    }
    __syncthreads();
    if (t < GG && bins[t] != 0.f) atomicAdd(&g_poolS[t], bins[t]);
}

// ---------------- finalize: mean pool; counts via binary search on sorted batch ----
__global__ void k_finalize(const int* __restrict__ batch, float* __restrict__ out) {
    int g = threadIdx.x;
    if (g < GG) {
        int lb0, lb1;
        { int lo = 0, hi = NN; while (lo < hi) { int m = (lo + hi) >> 1; if (batch[m] < g) lo = m + 1; else hi = m; } lb0 = lo; }
        { int lo = 0, hi = NN; while (lo < hi) { int m = (lo + hi) >> 1; if (batch[m] < g + 1) lo = m + 1; else hi = m; } lb1 = lo; }
        float c = (float)(lb1 - lb0);
        out[g] = (c > 0.f) ? (g_poolS[g] + g_poolT[g]) / c + g_e : 0.f;
    }
}

extern "C" void kernel_launch(void* const* d_in, const int* in_sizes, int n_in,
                              void* d_out, int out_size) {
    const float* x      = (const float*)d_in[0];
    const int*   ei     = (const int*)d_in[1];
    const int*   batch  = (const int*)d_in[2];
    const float* Wrel1  = (const float*)d_in[3];
    const float* brel1  = (const float*)d_in[4];
    const float* Wroot1 = (const float*)d_in[5];
    const float* Wrel2  = (const float*)d_in[6];
    const float* brel2  = (const float*)d_in[7];
    const float* Wroot2 = (const float*)d_in[8];
    const float* Wrel3  = (const float*)d_in[9];
    const float* brel3  = (const float*)d_in[10];
    const float* Wroot3 = (const float*)d_in[11];
    const float* c1w    = (const float*)d_in[12];
    const float* c1b    = (const float*)d_in[13];
    float* out = (float*)d_out;

    k_zero<<<ZB + 1, 256>>>(c1w, c1b, Wrel3, brel3, Wroot3);
    k_hist<<<GRID_E4, 256>>>(ei);
    k_scan<<<NT, 1024>>>();
    k_build<<<GRID_E4, 256>>>(ei);
    k_gc1<<<GRID_GC, 256>>>(x, Wrel1, brel1, Wroot1);
    k_gc2<<<GRID_GC, 256>>>(batch, Wrel2, brel2, Wroot2);
    k_scatter3<<<GRID_E4, 256>>>(ei, batch);
    k_finalize<<<1, 128>>>(batch, out);
}